// round 1
// baseline (speedup 1.0000x reference)
#include <cuda_runtime.h>
#include <cuda_bf16.h>
#include <math.h>

#define NN 50000
#define EE 800000
#define IN_DIM 128
#define HH 4
#define DD 32
#define NEG_SLOPE 0.2f
#define TN 8   // nodes per block tile in GEMM-ish kernels

// ---------------- scratch (device globals; no allocation allowed) ----------
__device__ float g_feat[(size_t)NN * IN_DIM];   // [N,128] = h @ W_fc
__device__ float g_el[NN * HH];
__device__ float g_er[NN * HH];
__device__ float g_denom[NN * HH];
__device__ float g_rst[(size_t)NN * IN_DIM];    // unnormalized aggregation

// ---------------- init: zero denom + rst ----------------
__global__ void k_init() {
    size_t total = (size_t)NN * IN_DIM + (size_t)NN * HH;
    for (size_t i = (size_t)blockIdx.x * blockDim.x + threadIdx.x; i < total;
         i += (size_t)gridDim.x * blockDim.x) {
        if (i < (size_t)NN * IN_DIM) g_rst[i] = 0.f;
        else g_denom[i - (size_t)NN * IN_DIM] = 0.f;
    }
}

// ---------------- feat = h @ W_fc  (50000x128 @ 128x128) ----------------
// block: 128 threads (one per output column), TN=8 nodes per block.
__global__ void k_feat(const float* __restrict__ h, const float* __restrict__ Wfc) {
    __shared__ float hs[TN][IN_DIM];
    int nb = blockIdx.x * TN;
    int j = threadIdx.x;
#pragma unroll
    for (int n = 0; n < TN; n++) {
        int node = nb + n;
        hs[n][j] = (node < NN) ? h[(size_t)node * IN_DIM + j] : 0.f;
    }
    __syncthreads();
    float acc[TN];
#pragma unroll
    for (int n = 0; n < TN; n++) acc[n] = 0.f;
#pragma unroll 4
    for (int k = 0; k < IN_DIM; k++) {
        float w = __ldg(&Wfc[k * IN_DIM + j]);
#pragma unroll
        for (int n = 0; n < TN; n++) acc[n] = fmaf(hs[n][k], w, acc[n]);
    }
#pragma unroll
    for (int n = 0; n < TN; n++) {
        int node = nb + n;
        if (node < NN) g_feat[(size_t)node * IN_DIM + j] = acc[n];
    }
}

// ---------------- el/er per node-head: one warp per node ----------------
__global__ void k_elr(const float* __restrict__ al, const float* __restrict__ ar) {
    int gw = (blockIdx.x * blockDim.x + threadIdx.x) >> 5;
    int lane = threadIdx.x & 31;
    if (gw >= NN) return;
    const float4* f4 = (const float4*)(g_feat + (size_t)gw * IN_DIM);
    float4 f = f4[lane];
    float4 a = ((const float4*)al)[lane];
    float4 b = ((const float4*)ar)[lane];
    float p = f.x * a.x + f.y * a.y + f.z * a.z + f.w * a.w;
    float q = f.x * b.x + f.y * b.y + f.z * b.z + f.w * b.w;
    // reduce within aligned groups of 8 lanes (one head per group: D=32 = 8 lanes * float4)
#pragma unroll
    for (int off = 4; off; off >>= 1) {
        p += __shfl_xor_sync(0xffffffffu, p, off);
        q += __shfl_xor_sync(0xffffffffu, q, off);
    }
    if ((lane & 7) == 0) {
        int hd = lane >> 3;
        g_el[gw * HH + hd] = p;
        g_er[gw * HH + hd] = q;
    }
}

// ---------------- edge pass: a = exp(leaky(el[s]+er[d])); denom += a;
//                  rst[d] += a * feat[s].  One warp per edge. ----------------
__global__ void k_edge(const int* __restrict__ src, const int* __restrict__ dst) {
    int gw = (blockIdx.x * blockDim.x + threadIdx.x) >> 5;
    if (gw >= EE) return;
    int lane = threadIdx.x & 31;
    int s = __ldg(&src[gw]);
    int d = __ldg(&dst[gw]);
    int hd = lane >> 3;   // head owning this lane's 4 columns
    float e = g_el[s * HH + hd] + g_er[d * HH + hd];
    e = (e > 0.f) ? e : NEG_SLOPE * e;
    float a = __expf(e);
    if ((lane & 7) == 0) atomicAdd(&g_denom[d * HH + hd], a);
    float4 f = ((const float4*)g_feat)[(size_t)s * (IN_DIM / 4) + lane];
    float* r = g_rst + (size_t)d * IN_DIM + lane * 4;
    atomicAdd(r + 0, f.x * a);
    atomicAdd(r + 1, f.y * a);
    atomicAdd(r + 2, f.z * a);
    atomicAdd(r + 3, f.w * a);
}

// ---------------- fused node epilogue:
//   hg = elu(rst/denom + bias_gat)
//   hp = hg @ W_proj + b_proj
//   g  = sigmoid([hp, ctx] @ W_gate + b_gate)
//   out = g*hp + (1-g)*ctx
// block: 128 threads, TN=8 nodes. ----------------
__global__ void k_node(const float* __restrict__ ctx,
                       const float* __restrict__ bgat,
                       const float* __restrict__ Wp, const float* __restrict__ bp,
                       const float* __restrict__ Wg, const float* __restrict__ bg,
                       float* __restrict__ out) {
    __shared__ float hg[TN][IN_DIM];
    __shared__ float hp[TN][IN_DIM];
    __shared__ float cs[TN][IN_DIM];
    int nb = blockIdx.x * TN;
    int j = threadIdx.x;
    float bgatj = __ldg(&bgat[j]);
#pragma unroll
    for (int n = 0; n < TN; n++) {
        int node = nb + n;
        if (node < NN) {
            float v = g_rst[(size_t)node * IN_DIM + j];
            float dh = g_denom[node * HH + (j >> 5)];
            float x = (dh > 0.f) ? (v / dh) : 0.f;
            x += bgatj;
            hg[n][j] = (x > 0.f) ? x : expm1f(x);     // elu
            cs[n][j] = ctx[(size_t)node * IN_DIM + j];
        } else {
            hg[n][j] = 0.f;
            cs[n][j] = 0.f;
        }
    }
    __syncthreads();

    // h_proj column j for 8 nodes
    float acc[TN];
#pragma unroll
    for (int n = 0; n < TN; n++) acc[n] = 0.f;
#pragma unroll 4
    for (int k = 0; k < IN_DIM; k++) {
        float w = __ldg(&Wp[k * IN_DIM + j]);
#pragma unroll
        for (int n = 0; n < TN; n++) acc[n] = fmaf(hg[n][k], w, acc[n]);
    }
    float bpj = __ldg(&bp[j]);
#pragma unroll
    for (int n = 0; n < TN; n++) {
        acc[n] += bpj;
        hp[n][j] = acc[n];
    }
    __syncthreads();

    // gate column j: first half uses hp, second half uses ctx
    float gacc[TN];
#pragma unroll
    for (int n = 0; n < TN; n++) gacc[n] = 0.f;
#pragma unroll 4
    for (int k = 0; k < IN_DIM; k++) {
        float w = __ldg(&Wg[k * IN_DIM + j]);
#pragma unroll
        for (int n = 0; n < TN; n++) gacc[n] = fmaf(hp[n][k], w, gacc[n]);
    }
#pragma unroll 4
    for (int k = 0; k < IN_DIM; k++) {
        float w = __ldg(&Wg[(IN_DIM + k) * IN_DIM + j]);
#pragma unroll
        for (int n = 0; n < TN; n++) gacc[n] = fmaf(cs[n][k], w, gacc[n]);
    }
    float bgj = __ldg(&bg[j]);
#pragma unroll
    for (int n = 0; n < TN; n++) {
        int node = nb + n;
        if (node < NN) {
            float g = 1.f / (1.f + __expf(-(gacc[n] + bgj)));
            out[(size_t)node * IN_DIM + j] = g * acc[n] + (1.f - g) * cs[n][j];
        }
    }
}

// ---------------- launch ----------------
extern "C" void kernel_launch(void* const* d_in, const int* in_sizes, int n_in,
                              void* d_out, int out_size) {
    const float* h    = (const float*)d_in[0];
    const int*   src  = (const int*)d_in[1];
    const int*   dst  = (const int*)d_in[2];
    const float* ctx  = (const float*)d_in[3];
    const float* Wfc  = (const float*)d_in[4];
    const float* al   = (const float*)d_in[5];
    const float* ar   = (const float*)d_in[6];
    const float* bgat = (const float*)d_in[7];
    const float* Wp   = (const float*)d_in[8];
    const float* bp   = (const float*)d_in[9];
    const float* Wg   = (const float*)d_in[10];
    const float* bg   = (const float*)d_in[11];
    float* out = (float*)d_out;

    k_init<<<1024, 256>>>();
    k_feat<<<(NN + TN - 1) / TN, IN_DIM>>>(h, Wfc);
    k_elr<<<(NN * 32 + 127) / 128, 128>>>(al, ar);
    k_edge<<<(EE * 32 + 255) / 256, 256>>>(src, dst);
    k_node<<<(NN + TN - 1) / TN, IN_DIM>>>(ctx, bgat, Wp, bp, Wg, bg, out);
}

// round 2
// speedup vs baseline: 1.2740x; 1.2740x over previous
#include <cuda_runtime.h>
#include <cuda_bf16.h>
#include <math.h>

#define NN 50000
#define EE 800000
#define IN_DIM 128
#define HH 4
#define NEG_SLOPE 0.2f
#define TN 8

// ---------------- scratch ----------------
__device__ float g_feat[(size_t)NN * IN_DIM];
__device__ float g_el[NN * HH];
__device__ float g_er[NN * HH];
__device__ float g_hg[(size_t)NN * IN_DIM];   // elu(agg + bias), GAT output
__device__ int   g_cnt[NN];                   // in-degree
__device__ int   g_off[NN];                   // CSR offsets
__device__ int   g_cur[NN];                   // scatter cursors
__device__ int   g_esrc[EE];                  // src node per CSR slot

// ---------------- init: zero counters ----------------
__global__ void k_init() {
    int i = blockIdx.x * blockDim.x + threadIdx.x;
    if (i < NN) { g_cnt[i] = 0; g_cur[i] = 0; }
}

// ---------------- feat = h @ W_fc, fused el/er ----------------
__global__ void k_feat(const float* __restrict__ h, const float* __restrict__ Wfc,
                       const float* __restrict__ al, const float* __restrict__ ar) {
    __shared__ float hs[TN][IN_DIM];
    int nb = blockIdx.x * TN;
    int j = threadIdx.x;
#pragma unroll
    for (int n = 0; n < TN; n++) {
        int node = nb + n;
        hs[n][j] = (node < NN) ? h[(size_t)node * IN_DIM + j] : 0.f;
    }
    __syncthreads();
    float acc[TN];
#pragma unroll
    for (int n = 0; n < TN; n++) acc[n] = 0.f;
#pragma unroll 4
    for (int k = 0; k < IN_DIM; k++) {
        float w = __ldg(&Wfc[k * IN_DIM + j]);
#pragma unroll
        for (int n = 0; n < TN; n++) acc[n] = fmaf(hs[n][k], w, acc[n]);
    }
    float alj = __ldg(&al[j]);   // attn_l flat [H*D] matches column index j
    float arj = __ldg(&ar[j]);
    int head = j >> 5;           // warp == head (block 128 threads)
    int lane = j & 31;
#pragma unroll
    for (int n = 0; n < TN; n++) {
        int node = nb + n;
        if (node < NN) g_feat[(size_t)node * IN_DIM + j] = acc[n];
        float pl = acc[n] * alj;
        float pr = acc[n] * arj;
#pragma unroll
        for (int off = 16; off; off >>= 1) {
            pl += __shfl_xor_sync(0xffffffffu, pl, off);
            pr += __shfl_xor_sync(0xffffffffu, pr, off);
        }
        if (lane == 0 && node < NN) {
            g_el[node * HH + head] = pl;
            g_er[node * HH + head] = pr;
        }
    }
}

// ---------------- CSR build ----------------
__global__ void k_hist(const int* __restrict__ dst) {
    int e = blockIdx.x * blockDim.x + threadIdx.x;
    if (e < EE) atomicAdd(&g_cnt[dst[e]], 1);
}

__global__ void k_scan() {   // single block, 1024 threads
    __shared__ int sums[1024];
    const int PER = (NN + 1023) / 1024;
    int t = threadIdx.x;
    int base = t * PER;
    int s = 0;
    for (int i = 0; i < PER; i++) {
        int idx = base + i;
        if (idx < NN) s += g_cnt[idx];
    }
    sums[t] = s;
    __syncthreads();
    for (int off = 1; off < 1024; off <<= 1) {
        int v = (t >= off) ? sums[t - off] : 0;
        __syncthreads();
        sums[t] += v;
        __syncthreads();
    }
    int run = (t == 0) ? 0 : sums[t - 1];
    for (int i = 0; i < PER; i++) {
        int idx = base + i;
        if (idx < NN) { g_off[idx] = run; run += g_cnt[idx]; }
    }
}

__global__ void k_scatter(const int* __restrict__ src, const int* __restrict__ dst) {
    int e = blockIdx.x * blockDim.x + threadIdx.x;
    if (e >= EE) return;
    int d = dst[e];
    int pos = atomicAdd(&g_cur[d], 1);
    g_esrc[g_off[d] + pos] = src[e];
}

// ---------------- aggregate: warp per node, no float atomics ----------------
__global__ void k_agg(const float* __restrict__ bgat) {
    int gw = (blockIdx.x * blockDim.x + threadIdx.x) >> 5;
    if (gw >= NN) return;
    int lane = threadIdx.x & 31;
    int beg = g_off[gw];
    int end = beg + g_cnt[gw];
    float er_h = (lane < HH) ? g_er[gw * HH + lane] : 0.f;
    int hd = lane >> 3;
    float4 acc = make_float4(0.f, 0.f, 0.f, 0.f);
    float dsum = 0.f;
    for (int i = beg; i < end; i++) {
        int s = __ldg(&g_esrc[i]);
        float a = 0.f;
        if (lane < HH) {
            float e = g_el[s * HH + lane] + er_h;
            e = (e > 0.f) ? e : NEG_SLOPE * e;
            a = __expf(e);
        }
        a = __shfl_sync(0xffffffffu, a, hd);
        dsum += a;
        float4 f = ((const float4*)g_feat)[(size_t)s * (IN_DIM / 4) + lane];
        acc.x = fmaf(f.x, a, acc.x);
        acc.y = fmaf(f.y, a, acc.y);
        acc.z = fmaf(f.z, a, acc.z);
        acc.w = fmaf(f.w, a, acc.w);
    }
    float inv = (dsum > 0.f) ? (1.f / dsum) : 0.f;
    float4 b = ((const float4*)bgat)[lane];
    float4 o;
    o.x = acc.x * inv + b.x; o.y = acc.y * inv + b.y;
    o.z = acc.z * inv + b.z; o.w = acc.w * inv + b.w;
    o.x = (o.x > 0.f) ? o.x : expm1f(o.x);
    o.y = (o.y > 0.f) ? o.y : expm1f(o.y);
    o.z = (o.z > 0.f) ? o.z : expm1f(o.z);
    o.w = (o.w > 0.f) ? o.w : expm1f(o.w);
    ((float4*)g_hg)[(size_t)gw * (IN_DIM / 4) + lane] = o;
}

// ---------------- node epilogue: proj + gate ----------------
__global__ void k_node(const float* __restrict__ ctx,
                       const float* __restrict__ Wp, const float* __restrict__ bp,
                       const float* __restrict__ Wg, const float* __restrict__ bg,
                       float* __restrict__ out) {
    __shared__ float hg[TN][IN_DIM];
    __shared__ float hp[TN][IN_DIM];
    __shared__ float cs[TN][IN_DIM];
    int nb = blockIdx.x * TN;
    int j = threadIdx.x;
#pragma unroll
    for (int n = 0; n < TN; n++) {
        int node = nb + n;
        if (node < NN) {
            hg[n][j] = g_hg[(size_t)node * IN_DIM + j];
            cs[n][j] = ctx[(size_t)node * IN_DIM + j];
        } else {
            hg[n][j] = 0.f;
            cs[n][j] = 0.f;
        }
    }
    __syncthreads();

    float acc[TN];
#pragma unroll
    for (int n = 0; n < TN; n++) acc[n] = 0.f;
#pragma unroll 4
    for (int k = 0; k < IN_DIM; k++) {
        float w = __ldg(&Wp[k * IN_DIM + j]);
#pragma unroll
        for (int n = 0; n < TN; n++) acc[n] = fmaf(hg[n][k], w, acc[n]);
    }
    float bpj = __ldg(&bp[j]);
#pragma unroll
    for (int n = 0; n < TN; n++) {
        acc[n] += bpj;
        hp[n][j] = acc[n];
    }
    __syncthreads();

    float gacc[TN];
#pragma unroll
    for (int n = 0; n < TN; n++) gacc[n] = 0.f;
#pragma unroll 4
    for (int k = 0; k < IN_DIM; k++) {
        float w = __ldg(&Wg[k * IN_DIM + j]);
#pragma unroll
        for (int n = 0; n < TN; n++) gacc[n] = fmaf(hp[n][k], w, gacc[n]);
    }
#pragma unroll 4
    for (int k = 0; k < IN_DIM; k++) {
        float w = __ldg(&Wg[(IN_DIM + k) * IN_DIM + j]);
#pragma unroll
        for (int n = 0; n < TN; n++) gacc[n] = fmaf(cs[n][k], w, gacc[n]);
    }
    float bgj = __ldg(&bg[j]);
#pragma unroll
    for (int n = 0; n < TN; n++) {
        int node = nb + n;
        if (node < NN) {
            float g = 1.f / (1.f + __expf(-(gacc[n] + bgj)));
            out[(size_t)node * IN_DIM + j] = g * acc[n] + (1.f - g) * cs[n][j];
        }
    }
}

// ---------------- launch ----------------
extern "C" void kernel_launch(void* const* d_in, const int* in_sizes, int n_in,
                              void* d_out, int out_size) {
    const float* h    = (const float*)d_in[0];
    const int*   src  = (const int*)d_in[1];
    const int*   dst  = (const int*)d_in[2];
    const float* ctx  = (const float*)d_in[3];
    const float* Wfc  = (const float*)d_in[4];
    const float* al   = (const float*)d_in[5];
    const float* ar   = (const float*)d_in[6];
    const float* bgat = (const float*)d_in[7];
    const float* Wp   = (const float*)d_in[8];
    const float* bp   = (const float*)d_in[9];
    const float* Wg   = (const float*)d_in[10];
    const float* bg   = (const float*)d_in[11];
    float* out = (float*)d_out;

    k_init<<<(NN + 255) / 256, 256>>>();
    k_hist<<<(EE + 255) / 256, 256>>>(dst);
    k_feat<<<(NN + TN - 1) / TN, IN_DIM>>>(h, Wfc, al, ar);
    k_scan<<<1, 1024>>>();
    k_scatter<<<(EE + 255) / 256, 256>>>(src, dst);
    k_agg<<<(NN * 32 + 255) / 256, 256>>>(bgat);
    k_node<<<(NN + TN - 1) / TN, IN_DIM>>>(ctx, Wp, bp, Wg, bg, out);
}

// round 3
// speedup vs baseline: 1.5611x; 1.2253x over previous
#include <cuda_runtime.h>
#include <cuda_bf16.h>
#include <math.h>

#define NN 50000
#define EE 800000
#define IN_DIM 128
#define HH 4
#define NEG_SLOPE 0.2f
#define TNF 16          // nodes per block in GEMM kernels (50000 = 3125*16 exact)
#define NBLK_SCAN 196   // ceil(50000/256)

typedef unsigned long long ull;

// ---------------- scratch ----------------
__device__ float g_feat[(size_t)NN * IN_DIM];
__device__ float g_el[NN * HH];
__device__ float g_er[NN * HH];
__device__ float g_hg[(size_t)NN * IN_DIM];
__device__ int   g_cnt[NN];
__device__ int   g_off[NN];
__device__ int   g_cur[NN];
__device__ int   g_esrc[EE];
__device__ int   g_bsum[256];

// ---------------- packed f32x2 helpers ----------------
__device__ __forceinline__ void ffma2(ull& acc, ull a, ull b) {
    asm("fma.rn.f32x2 %0, %1, %2, %3;" : "=l"(acc) : "l"(a), "l"(b), "l"(acc));
}
__device__ __forceinline__ ull pack2(float lo, float hi) {
    ull r; asm("mov.b64 %0, {%1, %2};" : "=l"(r) : "f"(lo), "f"(hi)); return r;
}
__device__ __forceinline__ void unpack2(ull v, float& lo, float& hi) {
    asm("mov.b64 {%0, %1}, %2;" : "=f"(lo), "=f"(hi) : "l"(v));
}

// ---------------- init ----------------
__global__ void k_init() {
    int i = blockIdx.x * blockDim.x + threadIdx.x;
    if (i < NN) { g_cnt[i] = 0; g_cur[i] = 0; }
}

// ---------------- feat = h @ W_fc : 64 thr, 2 cols x 16 nodes, packed ----
__global__ void k_feat(const float* __restrict__ h, const float* __restrict__ Wfc) {
    __shared__ __align__(16) float hs[IN_DIM][TNF + 2];
    int nb = blockIdx.x * TNF;
    int t = threadIdx.x;               // 0..63
#pragma unroll
    for (int n = 0; n < TNF; n++) {
        hs[t][n]      = h[(size_t)(nb + n) * IN_DIM + t];
        hs[t + 64][n] = h[(size_t)(nb + n) * IN_DIM + t + 64];
    }
    __syncthreads();
    ull acc0[8], acc1[8];
#pragma unroll
    for (int m = 0; m < 8; m++) { acc0[m] = 0ULL; acc1[m] = 0ULL; }
#pragma unroll 2
    for (int k = 0; k < IN_DIM; k++) {
        float w0 = __ldg(&Wfc[k * IN_DIM + t]);
        float w1 = __ldg(&Wfc[k * IN_DIM + t + 64]);
        ull wp0 = pack2(w0, w0), wp1 = pack2(w1, w1);
        const ull* row = (const ull*)&hs[k][0];
#pragma unroll
        for (int m = 0; m < 8; m++) {
            ull a = row[m];
            ffma2(acc0[m], a, wp0);
            ffma2(acc1[m], a, wp1);
        }
    }
#pragma unroll
    for (int m = 0; m < 8; m++) {
        float a, b, c, d;
        unpack2(acc0[m], a, b);
        unpack2(acc1[m], c, d);
        g_feat[(size_t)(nb + 2 * m)     * IN_DIM + t]      = a;
        g_feat[(size_t)(nb + 2 * m + 1) * IN_DIM + t]      = b;
        g_feat[(size_t)(nb + 2 * m)     * IN_DIM + t + 64] = c;
        g_feat[(size_t)(nb + 2 * m + 1) * IN_DIM + t + 64] = d;
    }
}

// ---------------- el/er: one warp per node ----------------
__global__ void k_elr(const float* __restrict__ al, const float* __restrict__ ar) {
    int gw = (blockIdx.x * blockDim.x + threadIdx.x) >> 5;
    int lane = threadIdx.x & 31;
    if (gw >= NN) return;
    float4 f = ((const float4*)g_feat)[(size_t)gw * (IN_DIM / 4) + lane];
    float4 a = ((const float4*)al)[lane];
    float4 b = ((const float4*)ar)[lane];
    float p = f.x * a.x + f.y * a.y + f.z * a.z + f.w * a.w;
    float q = f.x * b.x + f.y * b.y + f.z * b.z + f.w * b.w;
#pragma unroll
    for (int off = 4; off; off >>= 1) {
        p += __shfl_xor_sync(0xffffffffu, p, off);
        q += __shfl_xor_sync(0xffffffffu, q, off);
    }
    if ((lane & 7) == 0) {
        int hd = lane >> 3;
        g_el[gw * HH + hd] = p;
        g_er[gw * HH + hd] = q;
    }
}

// ---------------- CSR build ----------------
__global__ void k_hist(const int* __restrict__ dst) {
    int e = blockIdx.x * blockDim.x + threadIdx.x;
    if (e < EE) atomicAdd(&g_cnt[dst[e]], 1);
}

__global__ void k_scan1() {
    __shared__ int s[256];
    int i = blockIdx.x * 256 + threadIdx.x;
    int v = (i < NN) ? g_cnt[i] : 0;
    s[threadIdx.x] = v;
    __syncthreads();
#pragma unroll
    for (int off = 1; off < 256; off <<= 1) {
        int tv = (threadIdx.x >= off) ? s[threadIdx.x - off] : 0;
        __syncthreads();
        s[threadIdx.x] += tv;
        __syncthreads();
    }
    if (i < NN) g_off[i] = s[threadIdx.x] - v;
    if (threadIdx.x == 255) g_bsum[blockIdx.x] = s[255];
}

__global__ void k_scan2() {
    __shared__ int s[256];
    int t = threadIdx.x;
    int v = (t < NBLK_SCAN) ? g_bsum[t] : 0;
    s[t] = v;
    __syncthreads();
#pragma unroll
    for (int off = 1; off < 256; off <<= 1) {
        int tv = (t >= off) ? s[t - off] : 0;
        __syncthreads();
        s[t] += tv;
        __syncthreads();
    }
    if (t < NBLK_SCAN) g_bsum[t] = s[t] - v;
}

__global__ void k_scan3() {
    int i = blockIdx.x * 256 + threadIdx.x;
    if (i < NN) g_off[i] += g_bsum[blockIdx.x];
}

__global__ void k_scatter(const int* __restrict__ src, const int* __restrict__ dst) {
    int e = blockIdx.x * blockDim.x + threadIdx.x;
    if (e >= EE) return;
    int d = dst[e];
    int pos = atomicAdd(&g_cur[d], 1);
    g_esrc[g_off[d] + pos] = src[e];
}

// ---------------- aggregate: warp per node ----------------
__global__ void k_agg(const float* __restrict__ bgat) {
    int gw = (blockIdx.x * blockDim.x + threadIdx.x) >> 5;
    if (gw >= NN) return;
    int lane = threadIdx.x & 31;
    int beg = g_off[gw];
    int end = beg + g_cnt[gw];
    float er_h = (lane < HH) ? g_er[gw * HH + lane] : 0.f;
    int hd = lane >> 3;
    float4 acc = make_float4(0.f, 0.f, 0.f, 0.f);
    float dsum = 0.f;
    for (int i = beg; i < end; i++) {
        int s = __ldg(&g_esrc[i]);
        float a = 0.f;
        if (lane < HH) {
            float e = g_el[s * HH + lane] + er_h;
            e = (e > 0.f) ? e : NEG_SLOPE * e;
            a = __expf(e);
        }
        a = __shfl_sync(0xffffffffu, a, hd);
        dsum += a;
        float4 f = ((const float4*)g_feat)[(size_t)s * (IN_DIM / 4) + lane];
        acc.x = fmaf(f.x, a, acc.x);
        acc.y = fmaf(f.y, a, acc.y);
        acc.z = fmaf(f.z, a, acc.z);
        acc.w = fmaf(f.w, a, acc.w);
    }
    float inv = (dsum > 0.f) ? (1.f / dsum) : 0.f;
    float4 b = ((const float4*)bgat)[lane];
    float4 o;
    o.x = acc.x * inv + b.x; o.y = acc.y * inv + b.y;
    o.z = acc.z * inv + b.z; o.w = acc.w * inv + b.w;
    o.x = (o.x > 0.f) ? o.x : expm1f(o.x);
    o.y = (o.y > 0.f) ? o.y : expm1f(o.y);
    o.z = (o.z > 0.f) ? o.z : expm1f(o.z);
    o.w = (o.w > 0.f) ? o.w : expm1f(o.w);
    ((float4*)g_hg)[(size_t)gw * (IN_DIM / 4) + lane] = o;
}

// ---------------- node epilogue: proj + gate, packed ----------------
__global__ void k_node(const float* __restrict__ ctx,
                       const float* __restrict__ Wp, const float* __restrict__ bp,
                       const float* __restrict__ Wg, const float* __restrict__ bg,
                       float* __restrict__ out) {
    __shared__ __align__(16) float hg[IN_DIM][TNF + 2];
    __shared__ __align__(16) float cs[IN_DIM][TNF + 2];
    __shared__ __align__(16) float hp[IN_DIM][TNF + 2];
    int nb = blockIdx.x * TNF;
    int t = threadIdx.x;   // 0..63
#pragma unroll
    for (int n = 0; n < TNF; n++) {
        hg[t][n]      = g_hg[(size_t)(nb + n) * IN_DIM + t];
        hg[t + 64][n] = g_hg[(size_t)(nb + n) * IN_DIM + t + 64];
        cs[t][n]      = ctx[(size_t)(nb + n) * IN_DIM + t];
        cs[t + 64][n] = ctx[(size_t)(nb + n) * IN_DIM + t + 64];
    }
    __syncthreads();

    // GEMM1: h_proj
    ull p0[8], p1[8];
#pragma unroll
    for (int m = 0; m < 8; m++) { p0[m] = 0ULL; p1[m] = 0ULL; }
#pragma unroll 2
    for (int k = 0; k < IN_DIM; k++) {
        float w0 = __ldg(&Wp[k * IN_DIM + t]);
        float w1 = __ldg(&Wp[k * IN_DIM + t + 64]);
        ull wp0 = pack2(w0, w0), wp1 = pack2(w1, w1);
        const ull* row = (const ull*)&hg[k][0];
#pragma unroll
        for (int m = 0; m < 8; m++) {
            ull a = row[m];
            ffma2(p0[m], a, wp0);
            ffma2(p1[m], a, wp1);
        }
    }
    float bp0 = __ldg(&bp[t]), bp1 = __ldg(&bp[t + 64]);
    ull bpp0 = pack2(bp0, bp0), bpp1 = pack2(bp1, bp1);
    ull one = pack2(1.f, 1.f);
#pragma unroll
    for (int m = 0; m < 8; m++) {
        ffma2(p0[m], one, bpp0);   // p += 1*bias
        ffma2(p1[m], one, bpp1);
        float a, b, c, d;
        unpack2(p0[m], a, b);
        unpack2(p1[m], c, d);
        hp[t][2 * m] = a;      hp[t][2 * m + 1] = b;
        hp[t + 64][2 * m] = c; hp[t + 64][2 * m + 1] = d;
    }
    __syncthreads();

    // GEMM2: gate = [hp, cs] @ Wg
    ull q0[8], q1[8];
#pragma unroll
    for (int m = 0; m < 8; m++) { q0[m] = 0ULL; q1[m] = 0ULL; }
#pragma unroll 2
    for (int k = 0; k < IN_DIM; k++) {
        float w0 = __ldg(&Wg[k * IN_DIM + t]);
        float w1 = __ldg(&Wg[k * IN_DIM + t + 64]);
        ull wp0 = pack2(w0, w0), wp1 = pack2(w1, w1);
        const ull* row = (const ull*)&hp[k][0];
#pragma unroll
        for (int m = 0; m < 8; m++) {
            ull a = row[m];
            ffma2(q0[m], a, wp0);
            ffma2(q1[m], a, wp1);
        }
    }
#pragma unroll 2
    for (int k = 0; k < IN_DIM; k++) {
        float w0 = __ldg(&Wg[(IN_DIM + k) * IN_DIM + t]);
        float w1 = __ldg(&Wg[(IN_DIM + k) * IN_DIM + t + 64]);
        ull wp0 = pack2(w0, w0), wp1 = pack2(w1, w1);
        const ull* row = (const ull*)&cs[k][0];
#pragma unroll
        for (int m = 0; m < 8; m++) {
            ull a = row[m];
            ffma2(q0[m], a, wp0);
            ffma2(q1[m], a, wp1);
        }
    }
    float bg0 = __ldg(&bg[t]), bg1 = __ldg(&bg[t + 64]);
#pragma unroll
    for (int m = 0; m < 8; m++) {
        float ga, gb, gc, gd, ha, hb, hc, hd;
        unpack2(q0[m], ga, gb);
        unpack2(q1[m], gc, gd);
        unpack2(p0[m], ha, hb);
        unpack2(p1[m], hc, hd);
        float s0 = 1.f / (1.f + __expf(-(ga + bg0)));
        float s1 = 1.f / (1.f + __expf(-(gb + bg0)));
        float s2 = 1.f / (1.f + __expf(-(gc + bg1)));
        float s3 = 1.f / (1.f + __expf(-(gd + bg1)));
        float c0 = cs[t][2 * m],      c1 = cs[t][2 * m + 1];
        float c2 = cs[t + 64][2 * m], c3 = cs[t + 64][2 * m + 1];
        out[(size_t)(nb + 2 * m)     * IN_DIM + t]      = s0 * ha + (1.f - s0) * c0;
        out[(size_t)(nb + 2 * m + 1) * IN_DIM + t]      = s1 * hb + (1.f - s1) * c1;
        out[(size_t)(nb + 2 * m)     * IN_DIM + t + 64] = s2 * hc + (1.f - s2) * c2;
        out[(size_t)(nb + 2 * m + 1) * IN_DIM + t + 64] = s3 * hd + (1.f - s3) * c3;
    }
}

// ---------------- launch ----------------
extern "C" void kernel_launch(void* const* d_in, const int* in_sizes, int n_in,
                              void* d_out, int out_size) {
    const float* h    = (const float*)d_in[0];
    const int*   src  = (const int*)d_in[1];
    const int*   dst  = (const int*)d_in[2];
    const float* ctx  = (const float*)d_in[3];
    const float* Wfc  = (const float*)d_in[4];
    const float* al   = (const float*)d_in[5];
    const float* ar   = (const float*)d_in[6];
    const float* bgat = (const float*)d_in[7];
    const float* Wp   = (const float*)d_in[8];
    const float* bp   = (const float*)d_in[9];
    const float* Wg   = (const float*)d_in[10];
    const float* bg   = (const float*)d_in[11];
    float* out = (float*)d_out;

    k_init<<<(NN + 255) / 256, 256>>>();
    k_hist<<<(EE + 255) / 256, 256>>>(dst);
    k_feat<<<NN / TNF, 64>>>(h, Wfc);
    k_scan1<<<NBLK_SCAN, 256>>>();
    k_scan2<<<1, 256>>>();
    k_scan3<<<NBLK_SCAN, 256>>>();
    k_elr<<<(NN * 32 + 127) / 128, 128>>>(al, ar);
    k_scatter<<<(EE + 255) / 256, 256>>>(src, dst);
    k_agg<<<(NN * 32 + 255) / 256, 256>>>(bgat);
    k_node<<<NN / TNF, 64>>>(ctx, Wp, bp, Wg, bg, out);
}

// round 4
// speedup vs baseline: 1.6012x; 1.0257x over previous
#include <cuda_runtime.h>
#include <cuda_bf16.h>
#include <math.h>

#define NN 50000
#define EE 800000
#define IN_DIM 128
#define HH 4
#define NEG_SLOPE 0.2f
#define TNF 16          // nodes per block in GEMM kernels (50000 = 3125*16)
#define NBLK_SCAN 196   // ceil(50000/256)

typedef unsigned long long ull;

// ---------------- scratch ----------------
__device__ float g_feat[(size_t)NN * IN_DIM];
__device__ float g_el[NN * HH];
__device__ float g_er[NN * HH];
__device__ float g_hg[(size_t)NN * IN_DIM];
__device__ float g_wlr[IN_DIM * 8];           // [k][o]: o<4 -> wl head o, o>=4 -> wr head o-4
__device__ int   g_cnt[NN];
__device__ int   g_off[NN];                   // intra-block exclusive prefix
__device__ int   g_cur[NN];
__device__ int   g_esrc[EE];
__device__ int   g_bsum[256];                 // per-256-chunk exclusive sums

// ---------------- packed f32x2 helpers ----------------
__device__ __forceinline__ void ffma2(ull& acc, ull a, ull b) {
    asm("fma.rn.f32x2 %0, %1, %2, %3;" : "=l"(acc) : "l"(a), "l"(b), "l"(acc));
}
__device__ __forceinline__ ull pack2(float lo, float hi) {
    ull r; asm("mov.b64 %0, {%1, %2};" : "=l"(r) : "f"(lo), "f"(hi)); return r;
}
__device__ __forceinline__ void unpack2(ull v, float& lo, float& hi) {
    asm("mov.b64 {%0, %1}, %2;" : "=f"(lo), "=f"(hi) : "l"(v));
}

// ---------------- init ----------------
__global__ void k_init() {
    int i = blockIdx.x * blockDim.x + threadIdx.x;
    if (i < NN) { g_cnt[i] = 0; g_cur[i] = 0; }
}

// ---------------- prep: wl/wr = contraction of W_fc with attn vecs -------
__global__ void k_prep(const float* __restrict__ Wfc,
                       const float* __restrict__ al, const float* __restrict__ ar) {
    int t = threadIdx.x;   // 256 threads, 1024 outputs
#pragma unroll
    for (int it = 0; it < 4; it++) {
        int id = t + 256 * it;
        int k = id >> 3, o = id & 7;
        int head = o & 3;
        const float* av = (o < 4) ? al : ar;
        float s = 0.f;
#pragma unroll
        for (int d = 0; d < 32; d++)
            s = fmaf(__ldg(&Wfc[k * IN_DIM + head * 32 + d]), __ldg(&av[head * 32 + d]), s);
        g_wlr[id] = s;
    }
}

// ---------------- CSR histogram ----------------
__global__ void k_hist(const int* __restrict__ dst) {
    int e = blockIdx.x * blockDim.x + threadIdx.x;
    if (e < EE) atomicAdd(&g_cnt[dst[e]], 1);
}

// ---------------- feat = h @ W_fc (+ fused el/er) -------------------------
__global__ void k_feat(const float* __restrict__ h, const float* __restrict__ Wfc) {
    __shared__ __align__(16) float hs[IN_DIM][TNF + 2];
    __shared__ float wls[IN_DIM][8];
    int nb = blockIdx.x * TNF;
    int t = threadIdx.x;               // 0..63
#pragma unroll
    for (int n = 0; n < TNF; n++) {
        hs[t][n]      = h[(size_t)(nb + n) * IN_DIM + t];
        hs[t + 64][n] = h[(size_t)(nb + n) * IN_DIM + t + 64];
    }
#pragma unroll
    for (int it = 0; it < 16; it++) {
        int id = t + 64 * it;
        ((float*)wls)[id] = g_wlr[id];
    }
    __syncthreads();
    ull acc0[8], acc1[8], accE = 0ULL;
#pragma unroll
    for (int m = 0; m < 8; m++) { acc0[m] = 0ULL; acc1[m] = 0ULL; }
    int o = t & 7;          // which el/er output this thread computes
    int mp = t >> 3;        // node-pair index 0..7
#pragma unroll 2
    for (int k = 0; k < IN_DIM; k++) {
        float w0 = __ldg(&Wfc[k * IN_DIM + t]);
        float w1 = __ldg(&Wfc[k * IN_DIM + t + 64]);
        ull wp0 = pack2(w0, w0), wp1 = pack2(w1, w1);
        const ull* row = (const ull*)&hs[k][0];
        float we = wls[k][o];
        ffma2(accE, row[mp], pack2(we, we));
#pragma unroll
        for (int m = 0; m < 8; m++) {
            ull a = row[m];
            ffma2(acc0[m], a, wp0);
            ffma2(acc1[m], a, wp1);
        }
    }
#pragma unroll
    for (int m = 0; m < 8; m++) {
        float a, b, c, d;
        unpack2(acc0[m], a, b);
        unpack2(acc1[m], c, d);
        g_feat[(size_t)(nb + 2 * m)     * IN_DIM + t]      = a;
        g_feat[(size_t)(nb + 2 * m + 1) * IN_DIM + t]      = b;
        g_feat[(size_t)(nb + 2 * m)     * IN_DIM + t + 64] = c;
        g_feat[(size_t)(nb + 2 * m + 1) * IN_DIM + t + 64] = d;
    }
    float e0, e1;
    unpack2(accE, e0, e1);
    int head = o & 3;
    if (o < 4) {
        g_el[(nb + 2 * mp) * HH + head]     = e0;
        g_el[(nb + 2 * mp + 1) * HH + head] = e1;
    } else {
        g_er[(nb + 2 * mp) * HH + head]     = e0;
        g_er[(nb + 2 * mp + 1) * HH + head] = e1;
    }
}

// ---------------- scans ----------------
__global__ void k_scan1() {
    __shared__ int s[256];
    int i = blockIdx.x * 256 + threadIdx.x;
    int v = (i < NN) ? g_cnt[i] : 0;
    s[threadIdx.x] = v;
    __syncthreads();
#pragma unroll
    for (int off = 1; off < 256; off <<= 1) {
        int tv = (threadIdx.x >= off) ? s[threadIdx.x - off] : 0;
        __syncthreads();
        s[threadIdx.x] += tv;
        __syncthreads();
    }
    if (i < NN) g_off[i] = s[threadIdx.x] - v;
    if (threadIdx.x == 255) g_bsum[blockIdx.x] = s[255];
}

__global__ void k_scan2() {
    __shared__ int s[256];
    int t = threadIdx.x;
    int v = (t < NBLK_SCAN) ? g_bsum[t] : 0;
    s[t] = v;
    __syncthreads();
#pragma unroll
    for (int off = 1; off < 256; off <<= 1) {
        int tv = (t >= off) ? s[t - off] : 0;
        __syncthreads();
        s[t] += tv;
        __syncthreads();
    }
    if (t < NBLK_SCAN) g_bsum[t] = s[t] - v;
}

__global__ void k_scatter(const int* __restrict__ src, const int* __restrict__ dst) {
    int e = blockIdx.x * blockDim.x + threadIdx.x;
    if (e >= EE) return;
    int d = dst[e];
    int pos = atomicAdd(&g_cur[d], 1);
    g_esrc[g_off[d] + g_bsum[d >> 8] + pos] = src[e];
}

// ---------------- aggregate: warp per node, 2 edges/iter ----------------
__global__ void k_agg(const float* __restrict__ bgat) {
    int gw = (blockIdx.x * blockDim.x + threadIdx.x) >> 5;
    if (gw >= NN) return;
    int lane = threadIdx.x & 31;
    int beg = g_off[gw] + g_bsum[gw >> 8];
    int end = beg + g_cnt[gw];
    float er_h = (lane < HH) ? g_er[gw * HH + lane] : 0.f;
    // broadcast er to lanes 0..7 (lane&3 = head)
    float er8 = __shfl_sync(0xffffffffu, er_h, lane & 3);
    int hd = lane >> 3;
    float4 acc = make_float4(0.f, 0.f, 0.f, 0.f);
    float dsum = 0.f;
    int i = beg;
    for (; i + 1 < end; i += 2) {
        int s0 = __ldg(&g_esrc[i]);
        int s1 = __ldg(&g_esrc[i + 1]);
        float a = 0.f;
        if (lane < 8) {
            int sx = (lane < 4) ? s0 : s1;
            float e = g_el[sx * HH + (lane & 3)] + er8;
            e = (e > 0.f) ? e : NEG_SLOPE * e;
            a = __expf(e);
        }
        float a0 = __shfl_sync(0xffffffffu, a, hd);
        float a1 = __shfl_sync(0xffffffffu, a, hd + 4);
        dsum += a0 + a1;
        float4 f0 = ((const float4*)g_feat)[(size_t)s0 * (IN_DIM / 4) + lane];
        float4 f1 = ((const float4*)g_feat)[(size_t)s1 * (IN_DIM / 4) + lane];
        acc.x = fmaf(f0.x, a0, acc.x); acc.y = fmaf(f0.y, a0, acc.y);
        acc.z = fmaf(f0.z, a0, acc.z); acc.w = fmaf(f0.w, a0, acc.w);
        acc.x = fmaf(f1.x, a1, acc.x); acc.y = fmaf(f1.y, a1, acc.y);
        acc.z = fmaf(f1.z, a1, acc.z); acc.w = fmaf(f1.w, a1, acc.w);
    }
    if (i < end) {
        int s0 = __ldg(&g_esrc[i]);
        float a = 0.f;
        if (lane < 4) {
            float e = g_el[s0 * HH + lane] + er8;
            e = (e > 0.f) ? e : NEG_SLOPE * e;
            a = __expf(e);
        }
        float a0 = __shfl_sync(0xffffffffu, a, hd);
        dsum += a0;
        float4 f0 = ((const float4*)g_feat)[(size_t)s0 * (IN_DIM / 4) + lane];
        acc.x = fmaf(f0.x, a0, acc.x); acc.y = fmaf(f0.y, a0, acc.y);
        acc.z = fmaf(f0.z, a0, acc.z); acc.w = fmaf(f0.w, a0, acc.w);
    }
    float inv = (dsum > 0.f) ? (1.f / dsum) : 0.f;
    float4 b = ((const float4*)bgat)[lane];
    float4 o;
    o.x = acc.x * inv + b.x; o.y = acc.y * inv + b.y;
    o.z = acc.z * inv + b.z; o.w = acc.w * inv + b.w;
    o.x = (o.x > 0.f) ? o.x : expm1f(o.x);
    o.y = (o.y > 0.f) ? o.y : expm1f(o.y);
    o.z = (o.z > 0.f) ? o.z : expm1f(o.z);
    o.w = (o.w > 0.f) ? o.w : expm1f(o.w);
    ((float4*)g_hg)[(size_t)gw * (IN_DIM / 4) + lane] = o;
}

// ---------------- node epilogue: proj + gate, packed ----------------
__global__ void k_node(const float* __restrict__ ctx,
                       const float* __restrict__ Wp, const float* __restrict__ bp,
                       const float* __restrict__ Wg, const float* __restrict__ bg,
                       float* __restrict__ out) {
    __shared__ __align__(16) float hg[IN_DIM][TNF + 2];
    __shared__ __align__(16) float cs[IN_DIM][TNF + 2];
    __shared__ __align__(16) float hp[IN_DIM][TNF + 2];
    int nb = blockIdx.x * TNF;
    int t = threadIdx.x;   // 0..63
#pragma unroll
    for (int n = 0; n < TNF; n++) {
        hg[t][n]      = g_hg[(size_t)(nb + n) * IN_DIM + t];
        hg[t + 64][n] = g_hg[(size_t)(nb + n) * IN_DIM + t + 64];
        cs[t][n]      = ctx[(size_t)(nb + n) * IN_DIM + t];
        cs[t + 64][n] = ctx[(size_t)(nb + n) * IN_DIM + t + 64];
    }
    __syncthreads();

    ull p0[8], p1[8];
#pragma unroll
    for (int m = 0; m < 8; m++) { p0[m] = 0ULL; p1[m] = 0ULL; }
#pragma unroll 2
    for (int k = 0; k < IN_DIM; k++) {
        float w0 = __ldg(&Wp[k * IN_DIM + t]);
        float w1 = __ldg(&Wp[k * IN_DIM + t + 64]);
        ull wp0 = pack2(w0, w0), wp1 = pack2(w1, w1);
        const ull* row = (const ull*)&hg[k][0];
#pragma unroll
        for (int m = 0; m < 8; m++) {
            ull a = row[m];
            ffma2(p0[m], a, wp0);
            ffma2(p1[m], a, wp1);
        }
    }
    float bp0 = __ldg(&bp[t]), bp1 = __ldg(&bp[t + 64]);
    ull bpp0 = pack2(bp0, bp0), bpp1 = pack2(bp1, bp1);
    ull one = pack2(1.f, 1.f);
#pragma unroll
    for (int m = 0; m < 8; m++) {
        ffma2(p0[m], one, bpp0);
        ffma2(p1[m], one, bpp1);
        float a, b, c, d;
        unpack2(p0[m], a, b);
        unpack2(p1[m], c, d);
        hp[t][2 * m] = a;      hp[t][2 * m + 1] = b;
        hp[t + 64][2 * m] = c; hp[t + 64][2 * m + 1] = d;
    }
    __syncthreads();

    ull q0[8], q1[8];
#pragma unroll
    for (int m = 0; m < 8; m++) { q0[m] = 0ULL; q1[m] = 0ULL; }
#pragma unroll 2
    for (int k = 0; k < IN_DIM; k++) {
        float w0 = __ldg(&Wg[k * IN_DIM + t]);
        float w1 = __ldg(&Wg[k * IN_DIM + t + 64]);
        ull wp0 = pack2(w0, w0), wp1 = pack2(w1, w1);
        const ull* row = (const ull*)&hp[k][0];
#pragma unroll
        for (int m = 0; m < 8; m++) {
            ull a = row[m];
            ffma2(q0[m], a, wp0);
            ffma2(q1[m], a, wp1);
        }
    }
#pragma unroll 2
    for (int k = 0; k < IN_DIM; k++) {
        float w0 = __ldg(&Wg[(IN_DIM + k) * IN_DIM + t]);
        float w1 = __ldg(&Wg[(IN_DIM + k) * IN_DIM + t + 64]);
        ull wp0 = pack2(w0, w0), wp1 = pack2(w1, w1);
        const ull* row = (const ull*)&cs[k][0];
#pragma unroll
        for (int m = 0; m < 8; m++) {
            ull a = row[m];
            ffma2(q0[m], a, wp0);
            ffma2(q1[m], a, wp1);
        }
    }
    float bg0 = __ldg(&bg[t]), bg1 = __ldg(&bg[t + 64]);
#pragma unroll
    for (int m = 0; m < 8; m++) {
        float ga, gb, gc, gd, ha, hb, hc, hd;
        unpack2(q0[m], ga, gb);
        unpack2(q1[m], gc, gd);
        unpack2(p0[m], ha, hb);
        unpack2(p1[m], hc, hd);
        float s0 = 1.f / (1.f + __expf(-(ga + bg0)));
        float s1 = 1.f / (1.f + __expf(-(gb + bg0)));
        float s2 = 1.f / (1.f + __expf(-(gc + bg1)));
        float s3 = 1.f / (1.f + __expf(-(gd + bg1)));
        float c0 = cs[t][2 * m],      c1 = cs[t][2 * m + 1];
        float c2 = cs[t + 64][2 * m], c3 = cs[t + 64][2 * m + 1];
        out[(size_t)(nb + 2 * m)     * IN_DIM + t]      = s0 * ha + (1.f - s0) * c0;
        out[(size_t)(nb + 2 * m + 1) * IN_DIM + t]      = s1 * hb + (1.f - s1) * c1;
        out[(size_t)(nb + 2 * m)     * IN_DIM + t + 64] = s2 * hc + (1.f - s2) * c2;
        out[(size_t)(nb + 2 * m + 1) * IN_DIM + t + 64] = s3 * hd + (1.f - s3) * c3;
    }
}

// ---------------- launch ----------------
extern "C" void kernel_launch(void* const* d_in, const int* in_sizes, int n_in,
                              void* d_out, int out_size) {
    const float* h    = (const float*)d_in[0];
    const int*   src  = (const int*)d_in[1];
    const int*   dst  = (const int*)d_in[2];
    const float* ctx  = (const float*)d_in[3];
    const float* Wfc  = (const float*)d_in[4];
    const float* al   = (const float*)d_in[5];
    const float* ar   = (const float*)d_in[6];
    const float* bgat = (const float*)d_in[7];
    const float* Wp   = (const float*)d_in[8];
    const float* bp   = (const float*)d_in[9];
    const float* Wg   = (const float*)d_in[10];
    const float* bg   = (const float*)d_in[11];
    float* out = (float*)d_out;

    k_init<<<(NN + 255) / 256, 256>>>();            // 1
    k_hist<<<(EE + 255) / 256, 256>>>(dst);         // 2
    k_prep<<<1, 256>>>(Wfc, al, ar);                // 3
    k_feat<<<NN / TNF, 64>>>(h, Wfc);               // 4 <- profiled slot
    k_scan1<<<NBLK_SCAN, 256>>>();                  // 5
    k_scan2<<<1, 256>>>();                          // 6
    k_scatter<<<(EE + 255) / 256, 256>>>(src, dst); // 7
    k_agg<<<(NN * 32 + 255) / 256, 256>>>(bgat);    // 8
    k_node<<<NN / TNF, 64>>>(ctx, Wp, bp, Wg, bg, out); // 9
}